// round 3
// baseline (speedup 1.0000x reference)
#include <cuda_runtime.h>
#include <cuda_fp16.h>
#include <cstdint>

#define T_TOK 4096
#define D_IN  2048
#define D_MOE 768
#define TWO_DM 1536

#define BM 128
#define BN 64
#define BK 32
#define LDA 40   // BK + 8 pad (keeps 16B alignment: 40*2=80B row stride)

// Scratch (device globals: allocation-free per harness rules)
__device__ __align__(16) __half g_xh[T_TOK * D_IN];      // 16 MB
__device__ __align__(16) __half g_guw[TWO_DM * D_IN];    //  6 MB
__device__ __align__(16) __half g_dw[D_IN * D_MOE];      //  3 MB
__device__ __align__(16) __half g_h[T_TOK * D_MOE];      //  6 MB

// ---------------------------------------------------------------------------
// fp32 -> fp16 conversion of x and the selected expert's weights.
// expert_idx lives in device memory; indexing must be done on-GPU.
// ---------------------------------------------------------------------------
__global__ void convert_kernel(const float* __restrict__ x,
                               const float* __restrict__ gup,
                               const float* __restrict__ dp,
                               const int* __restrict__ eidx) {
    const int e = *eidx;
    const float* gu = gup + (size_t)e * TWO_DM * D_IN;
    const float* dw = dp  + (size_t)e * D_IN * D_MOE;
    const int stride = gridDim.x * blockDim.x;
    const int tid = blockIdx.x * blockDim.x + threadIdx.x;

    const int nx = T_TOK * D_IN / 2;
    for (int i = tid; i < nx; i += stride) {
        float2 v = ((const float2*)x)[i];
        ((__half2*)g_xh)[i] = __floats2half2_rn(v.x, v.y);
    }
    const int ng = TWO_DM * D_IN / 2;
    for (int i = tid; i < ng; i += stride) {
        float2 v = ((const float2*)gu)[i];
        ((__half2*)g_guw)[i] = __floats2half2_rn(v.x, v.y);
    }
    const int nd = D_IN * D_MOE / 2;
    for (int i = tid; i < nd; i += stride) {
        float2 v = ((const float2*)dw)[i];
        ((__half2*)g_dw)[i] = __floats2half2_rn(v.x, v.y);
    }
}

// ---------------------------------------------------------------------------
// m16n8k16 f16 MMA, fp32 accumulate
// ---------------------------------------------------------------------------
__device__ __forceinline__ void mma_16816(float* c, const uint32_t* a, const uint32_t* b) {
    asm volatile(
        "mma.sync.aligned.m16n8k16.row.col.f32.f16.f16.f32 "
        "{%0,%1,%2,%3}, {%4,%5,%6,%7}, {%8,%9}, {%0,%1,%2,%3};"
        : "+f"(c[0]), "+f"(c[1]), "+f"(c[2]), "+f"(c[3])
        : "r"(a[0]), "r"(a[1]), "r"(a[2]), "r"(a[3]), "r"(b[0]), "r"(b[1]));
}

__device__ __forceinline__ float silu_f(float v) {
    return v / (1.0f + __expf(-v));
}

// ---------------------------------------------------------------------------
// GEMM1 + fused SwiGLU: gu = x @ gu_w^T ; h = silu(gate)*up  -> g_h (fp16)
// Each CTA computes a 128x64 tile of gate AND the matching up tile (+768 rows
// of B), so SwiGLU fuses in registers. A-tile smem is shared between both.
// ---------------------------------------------------------------------------
__global__ __launch_bounds__(256, 2) void gemm1_swiglu_kernel() {
    __shared__ __half As[BM][LDA];
    __shared__ __half Bg[BN][LDA];
    __shared__ __half Bu[BN][LDA];

    const int tid = threadIdx.x;
    const int bm = blockIdx.y, bn = blockIdx.x;
    const int warp = tid >> 5, lane = tid & 31;
    const int wm = warp & 3, wn = warp >> 2;      // 4 warps along M, 2 along N
    const int g = lane >> 2, q = lane & 3;

    float accg[2][4][4], accu[2][4][4];
#pragma unroll
    for (int i = 0; i < 2; i++)
#pragma unroll
        for (int j = 0; j < 4; j++)
#pragma unroll
            for (int k = 0; k < 4; k++) { accg[i][j][k] = 0.f; accu[i][j][k] = 0.f; }

    const __half* Ap  = g_xh  + (size_t)(bm * BM) * D_IN;
    const __half* Bgp = g_guw + (size_t)(bn * BN) * D_IN;
    const __half* Bup = g_guw + (size_t)(D_MOE + bn * BN) * D_IN;

    for (int kt = 0; kt < D_IN; kt += BK) {
        __syncthreads();
        // A: 128x32 halves = 512 uint4, 2 per thread
#pragma unroll
        for (int i = 0; i < 2; i++) {
            int idx = tid + i * 256;
            int r = idx >> 2, c = (idx & 3) << 3;
            *(uint4*)&As[r][c] = *(const uint4*)&Ap[(size_t)r * D_IN + kt + c];
        }
        // B gate + up: 64x32 each = 256 uint4 each, 1 per thread each
        {
            int r = tid >> 2, c = (tid & 3) << 3;
            *(uint4*)&Bg[r][c] = *(const uint4*)&Bgp[(size_t)r * D_IN + kt + c];
            *(uint4*)&Bu[r][c] = *(const uint4*)&Bup[(size_t)r * D_IN + kt + c];
        }
        __syncthreads();

#pragma unroll
        for (int kk = 0; kk < BK; kk += 16) {
            uint32_t a[2][4];
#pragma unroll
            for (int mi = 0; mi < 2; mi++) {
                int row = wm * 32 + mi * 16 + g;
                a[mi][0] = *(const uint32_t*)&As[row][kk + q * 2];
                a[mi][1] = *(const uint32_t*)&As[row + 8][kk + q * 2];
                a[mi][2] = *(const uint32_t*)&As[row][kk + q * 2 + 8];
                a[mi][3] = *(const uint32_t*)&As[row + 8][kk + q * 2 + 8];
            }
            uint32_t bg[4][2], bu[4][2];
#pragma unroll
            for (int ni = 0; ni < 4; ni++) {
                int n0 = wn * 32 + ni * 8 + g;
                bg[ni][0] = *(const uint32_t*)&Bg[n0][kk + q * 2];
                bg[ni][1] = *(const uint32_t*)&Bg[n0][kk + q * 2 + 8];
                bu[ni][0] = *(const uint32_t*)&Bu[n0][kk + q * 2];
                bu[ni][1] = *(const uint32_t*)&Bu[n0][kk + q * 2 + 8];
            }
#pragma unroll
            for (int mi = 0; mi < 2; mi++)
#pragma unroll
                for (int ni = 0; ni < 4; ni++) {
                    mma_16816(accg[mi][ni], a[mi], bg[ni]);
                    mma_16816(accu[mi][ni], a[mi], bu[ni]);
                }
        }
    }

    // Epilogue: SwiGLU + fp16 store of h
    const int rowbase = bm * BM + wm * 32;
#pragma unroll
    for (int mi = 0; mi < 2; mi++)
#pragma unroll
        for (int ni = 0; ni < 4; ni++) {
            int r0 = rowbase + mi * 16 + g;
            int cl = wn * 32 + ni * 8 + q * 2;       // col within tile
            int gc = bn * BN + cl;                    // global h col
            float* cg = accg[mi][ni];
            float* cu = accu[mi][ni];
            float h0 = silu_f(cg[0]) * cu[0];
            float h1 = silu_f(cg[1]) * cu[1];
            float h2 = silu_f(cg[2]) * cu[2];
            float h3 = silu_f(cg[3]) * cu[3];
            *(__half2*)&g_h[(size_t)r0 * D_MOE + gc]       = __floats2half2_rn(h0, h1);
            *(__half2*)&g_h[(size_t)(r0 + 8) * D_MOE + gc] = __floats2half2_rn(h2, h3);
        }
}

// ---------------------------------------------------------------------------
// GEMM2: out = h @ down_w^T   (M=4096, N=2048, K=768), fp32 out
// ---------------------------------------------------------------------------
__global__ __launch_bounds__(256, 2) void gemm2_kernel(float* __restrict__ out) {
    __shared__ __half As[BM][LDA];
    __shared__ __half Bs[BN][LDA];

    const int tid = threadIdx.x;
    const int bm = blockIdx.y, bn = blockIdx.x;
    const int warp = tid >> 5, lane = tid & 31;
    const int wm = warp & 3, wn = warp >> 2;
    const int g = lane >> 2, q = lane & 3;

    float acc[2][4][4];
#pragma unroll
    for (int i = 0; i < 2; i++)
#pragma unroll
        for (int j = 0; j < 4; j++)
#pragma unroll
            for (int k = 0; k < 4; k++) acc[i][j][k] = 0.f;

    const __half* Ap = g_h  + (size_t)(bm * BM) * D_MOE;
    const __half* Bp = g_dw + (size_t)(bn * BN) * D_MOE;

    for (int kt = 0; kt < D_MOE; kt += BK) {
        __syncthreads();
#pragma unroll
        for (int i = 0; i < 2; i++) {
            int idx = tid + i * 256;
            int r = idx >> 2, c = (idx & 3) << 3;
            *(uint4*)&As[r][c] = *(const uint4*)&Ap[(size_t)r * D_MOE + kt + c];
        }
        {
            int r = tid >> 2, c = (tid & 3) << 3;
            *(uint4*)&Bs[r][c] = *(const uint4*)&Bp[(size_t)r * D_MOE + kt + c];
        }
        __syncthreads();

#pragma unroll
        for (int kk = 0; kk < BK; kk += 16) {
            uint32_t a[2][4];
#pragma unroll
            for (int mi = 0; mi < 2; mi++) {
                int row = wm * 32 + mi * 16 + g;
                a[mi][0] = *(const uint32_t*)&As[row][kk + q * 2];
                a[mi][1] = *(const uint32_t*)&As[row + 8][kk + q * 2];
                a[mi][2] = *(const uint32_t*)&As[row][kk + q * 2 + 8];
                a[mi][3] = *(const uint32_t*)&As[row + 8][kk + q * 2 + 8];
            }
            uint32_t b[4][2];
#pragma unroll
            for (int ni = 0; ni < 4; ni++) {
                int n0 = wn * 32 + ni * 8 + g;
                b[ni][0] = *(const uint32_t*)&Bs[n0][kk + q * 2];
                b[ni][1] = *(const uint32_t*)&Bs[n0][kk + q * 2 + 8];
            }
#pragma unroll
            for (int mi = 0; mi < 2; mi++)
#pragma unroll
                for (int ni = 0; ni < 4; ni++)
                    mma_16816(acc[mi][ni], a[mi], b[ni]);
        }
    }

    const int rowbase = bm * BM + wm * 32;
#pragma unroll
    for (int mi = 0; mi < 2; mi++)
#pragma unroll
        for (int ni = 0; ni < 4; ni++) {
            int r0 = rowbase + mi * 16 + g;
            int gc = bn * BN + wn * 32 + ni * 8 + q * 2;
            float* c = acc[mi][ni];
            *(float2*)&out[(size_t)r0 * D_IN + gc]       = make_float2(c[0], c[1]);
            *(float2*)&out[(size_t)(r0 + 8) * D_IN + gc] = make_float2(c[2], c[3]);
        }
}

// ---------------------------------------------------------------------------
extern "C" void kernel_launch(void* const* d_in, const int* in_sizes, int n_in,
                              void* d_out, int out_size) {
    const float* x   = (const float*)d_in[0];
    const float* gup = (const float*)d_in[1];
    const float* dp  = (const float*)d_in[2];
    const int* eidx  = (const int*)d_in[3];
    float* out = (float*)d_out;

    convert_kernel<<<1024, 256>>>(x, gup, dp, eidx);
    gemm1_swiglu_kernel<<<dim3(D_MOE / BN, T_TOK / BM), 256>>>();
    gemm2_kernel<<<dim3(D_IN / BN, T_TOK / BM), 256>>>(out);
}

// round 6
// speedup vs baseline: 1.5490x; 1.5490x over previous
#include <cuda_runtime.h>
#include <cuda_fp16.h>
#include <cstdint>

#define T_TOK 4096
#define D_IN  2048
#define D_MOE 768
#define TWO_DM 1536

// ---- tiling ----
#define BM 128
#define BK 64                       // halves per K chunk = 128B swizzled row
#define A_BYTES  (BM * 128)         // 16 KB
#define B_BYTES  (128 * 128)        // 16 KB (128 B-rows)
#define STAGE_BYTES (A_BYTES + B_BYTES)
#define S_STAGES 3
#define SMEM_TOTAL (S_STAGES * STAGE_BYTES)   // 96 KB

// Scratch (device globals: allocation-free per harness rules)
__device__ __align__(16) __half g_xh[T_TOK * D_IN];      // 16 MB
__device__ __align__(16) __half g_guw[TWO_DM * D_IN];    //  6 MB
__device__ __align__(16) __half g_dw[D_IN * D_MOE];      //  3 MB
__device__ __align__(16) __half g_h[T_TOK * D_MOE];      //  6 MB

// ---------------------------------------------------------------------------
// PTX helpers (all non-'a' features: cp.async sm_80, ldmatrix sm_75, mma sm_80)
// ---------------------------------------------------------------------------
__device__ __forceinline__ uint32_t smem_u32(const void* p) {
    uint32_t a;
    asm("{ .reg .u64 t; cvta.to.shared.u64 t, %1; cvt.u32.u64 %0, t; }" : "=r"(a) : "l"(p));
    return a;
}
__device__ __forceinline__ void cp16(uint32_t saddr, const void* gaddr) {
    asm volatile("cp.async.cg.shared.global [%0], [%1], 16;" :: "r"(saddr), "l"(gaddr));
}
#define CP_COMMIT() asm volatile("cp.async.commit_group;" ::: "memory")
#define CP_WAIT(n)  asm volatile("cp.async.wait_group %0;" :: "n"(n) : "memory")

__device__ __forceinline__ void ldsm_x4(uint32_t& r0, uint32_t& r1, uint32_t& r2, uint32_t& r3,
                                        uint32_t addr) {
    asm volatile("ldmatrix.sync.aligned.m8n8.x4.shared.b16 {%0,%1,%2,%3}, [%4];"
                 : "=r"(r0), "=r"(r1), "=r"(r2), "=r"(r3) : "r"(addr));
}
__device__ __forceinline__ void mma_16816(float* c, const uint32_t* a, const uint32_t* b) {
    asm volatile(
        "mma.sync.aligned.m16n8k16.row.col.f32.f16.f16.f32 "
        "{%0,%1,%2,%3}, {%4,%5,%6,%7}, {%8,%9}, {%0,%1,%2,%3};"
        : "+f"(c[0]), "+f"(c[1]), "+f"(c[2]), "+f"(c[3])
        : "r"(a[0]), "r"(a[1]), "r"(a[2]), "r"(a[3]), "r"(b[0]), "r"(b[1]));
}
__device__ __forceinline__ float silu_f(float v) { return v / (1.0f + __expf(-v)); }

// ---------------------------------------------------------------------------
// fp32 -> fp16 conversion (float4 vectorized). expert_idx read on device.
// ---------------------------------------------------------------------------
__global__ void convert_kernel(const float* __restrict__ x,
                               const float* __restrict__ gup,
                               const float* __restrict__ dp,
                               const int* __restrict__ eidx) {
    const int e = *eidx;
    const float4* gu4 = (const float4*)(gup + (size_t)e * TWO_DM * D_IN);
    const float4* dw4 = (const float4*)(dp + (size_t)e * D_IN * D_MOE);
    const float4* x4 = (const float4*)x;
    uint2* xo = (uint2*)g_xh;
    uint2* go = (uint2*)g_guw;
    uint2* do_ = (uint2*)g_dw;
    const int stride = gridDim.x * blockDim.x;
    const int tid = blockIdx.x * blockDim.x + threadIdx.x;

    const int nx = T_TOK * D_IN / 4;
    for (int i = tid; i < nx; i += stride) {
        float4 v = x4[i];
        __half2 a = __floats2half2_rn(v.x, v.y), b = __floats2half2_rn(v.z, v.w);
        xo[i] = make_uint2(*(uint32_t*)&a, *(uint32_t*)&b);
    }
    const int ng = TWO_DM * D_IN / 4;
    for (int i = tid; i < ng; i += stride) {
        float4 v = gu4[i];
        __half2 a = __floats2half2_rn(v.x, v.y), b = __floats2half2_rn(v.z, v.w);
        go[i] = make_uint2(*(uint32_t*)&a, *(uint32_t*)&b);
    }
    const int nd = D_IN * D_MOE / 4;
    for (int i = tid; i < nd; i += stride) {
        float4 v = dw4[i];
        __half2 a = __floats2half2_rn(v.x, v.y), b = __floats2half2_rn(v.z, v.w);
        do_[i] = make_uint2(*(uint32_t*)&a, *(uint32_t*)&b);
    }
}

// ---------------------------------------------------------------------------
// Pipelined HMMA GEMM. 256 threads = 8 warps (4 along M x 2 along N).
// Tiles: A 128x64, B 128 rows x 64 (G1: 64 gate + 64 up rows; G2: 128 n rows).
// 3-stage cp.async ring; SW128 swizzle; ldmatrix.x4 fragment loads.
// IS_G1 epilogue: SwiGLU -> g_h (fp16). else: fp32 -> out.
// ---------------------------------------------------------------------------
template <int KDIM, int NCHUNK, bool IS_G1>
__global__ __launch_bounds__(256, 1) void gemm_hmma(float* __restrict__ out) {
    extern __shared__ char smem[];
    const uint32_t sbase = smem_u32(smem);
    const int tid = threadIdx.x, wid = tid >> 5, lane = tid & 31;
    const int wm = wid & 3, wn = wid >> 2;
    const int g = lane >> 2, q = lane & 3;
    const int bn = blockIdx.x, bm = blockIdx.y;

    const __half *Ap, *Bg, *Bu, *Bp;
    if (IS_G1) {
        Ap = g_xh + (size_t)bm * BM * KDIM;
        Bg = g_guw + (size_t)(bn * 64) * KDIM;
        Bu = g_guw + (size_t)(D_MOE + bn * 64) * KDIM;
        Bp = nullptr;
    } else {
        Ap = g_h + (size_t)bm * BM * KDIM;
        Bp = g_dw + (size_t)(bn * 128) * KDIM;
        Bg = Bu = nullptr;
    }

    // ---- stage loader: A 1024 + B 1024 granules of 16B, 8 cp.async/thread ----
    auto load_stage = [&](int stage, int chunk) {
        const uint32_t sA = sbase + stage * STAGE_BYTES;
        const uint32_t sB = sA + A_BYTES;
        const int k0 = chunk * BK;
#pragma unroll
        for (int i = 0; i < 4; i++) {
            int gi = tid + i * 256;
            int r = gi >> 3, c = gi & 7;
            cp16(sA + r * 128 + ((c ^ (r & 7)) << 4), Ap + (size_t)r * KDIM + k0 + c * 8);
        }
#pragma unroll
        for (int i = 0; i < 4; i++) {
            int gi = tid + i * 256;
            int r = gi >> 3, c = gi & 7;
            const __half* src;
            if (IS_G1)
                src = (r < 64) ? (Bg + (size_t)r * KDIM) : (Bu + (size_t)(r - 64) * KDIM);
            else
                src = Bp + (size_t)r * KDIM;
            cp16(sB + r * 128 + ((c ^ (r & 7)) << 4), src + k0 + c * 8);
        }
        CP_COMMIT();
    };

    // ldmatrix lane address components
    const int r7 = lane & 7;
    const int laneRowA = ((lane >> 3) & 1) * 8 + r7;  // + ksel = lane>>4
    const int kselA = lane >> 4;
    const int laneRowB = (lane >> 4) * 8 + r7;        // + ksel = (lane>>3)&1
    const int kselB = (lane >> 3) & 1;

    float acc[2][8][4];
#pragma unroll
    for (int a = 0; a < 2; a++)
#pragma unroll
        for (int b = 0; b < 8; b++)
#pragma unroll
            for (int c = 0; c < 4; c++) acc[a][b][c] = 0.f;

    // ---- pipeline ----
    load_stage(0, 0);
    load_stage(1, 1);

    for (int j = 0; j < NCHUNK; j++) {
        if (j == NCHUNK - 1) { CP_WAIT(0); } else { CP_WAIT(1); }
        __syncthreads();
        if (j + 2 < NCHUNK) load_stage((j + 2) % S_STAGES, j + 2);

        const uint32_t sA = sbase + (j % S_STAGES) * STAGE_BYTES;
        const uint32_t sB = sA + A_BYTES;

#pragma unroll
        for (int kk = 0; kk < 4; kk++) {
            // A fragments: 2 m16 tiles
            uint32_t a[2][4];
#pragma unroll
            for (int mt = 0; mt < 2; mt++) {
                int row = wm * 32 + mt * 16 + laneRowA;
                uint32_t addr = sA + row * 128 + (((kk * 2 + kselA) ^ r7) << 4);
                ldsm_x4(a[mt][0], a[mt][1], a[mt][2], a[mt][3], addr);
            }
            // B fragments: 8 n8 tiles via 4 ldmatrix.x4
            uint32_t b[8][2];
#pragma unroll
            for (int p = 0; p < 4; p++) {
                int nbase;
                if (IS_G1) nbase = (p < 2) ? (wn * 32 + p * 16) : (64 + wn * 32 + (p - 2) * 16);
                else       nbase = wn * 64 + p * 16;
                int row = nbase + laneRowB;
                uint32_t addr = sB + row * 128 + (((kk * 2 + kselB) ^ r7) << 4);
                ldsm_x4(b[2 * p][0], b[2 * p][1], b[2 * p + 1][0], b[2 * p + 1][1], addr);
            }
#pragma unroll
            for (int mt = 0; mt < 2; mt++)
#pragma unroll
                for (int ni = 0; ni < 8; ni++)
                    mma_16816(acc[mt][ni], a[mt], b[ni]);
        }
    }

    // ---- epilogue ----
    if (IS_G1) {
        // acc[][0..3] = gate (cols wn*32 + ni*8), acc[][4..7] = up (same cols)
#pragma unroll
        for (int mt = 0; mt < 2; mt++)
#pragma unroll
            for (int ni = 0; ni < 4; ni++) {
                int row = bm * BM + wm * 32 + mt * 16 + g;
                int col = bn * 64 + wn * 32 + ni * 8 + q * 2;
                float* cg = acc[mt][ni];
                float* cu = acc[mt][ni + 4];
                __half2 h01 = __floats2half2_rn(silu_f(cg[0]) * cu[0], silu_f(cg[1]) * cu[1]);
                __half2 h23 = __floats2half2_rn(silu_f(cg[2]) * cu[2], silu_f(cg[3]) * cu[3]);
                *(__half2*)&g_h[(size_t)row * D_MOE + col] = h01;
                *(__half2*)&g_h[(size_t)(row + 8) * D_MOE + col] = h23;
            }
    } else {
#pragma unroll
        for (int mt = 0; mt < 2; mt++)
#pragma unroll
            for (int ni = 0; ni < 8; ni++) {
                int row = bm * BM + wm * 32 + mt * 16 + g;
                int col = bn * 128 + wn * 64 + ni * 8 + q * 2;
                float* c = acc[mt][ni];
                *(float2*)&out[(size_t)row * D_IN + col] = make_float2(c[0], c[1]);
                *(float2*)&out[(size_t)(row + 8) * D_IN + col] = make_float2(c[2], c[3]);
            }
    }
}

// ---------------------------------------------------------------------------
extern "C" void kernel_launch(void* const* d_in, const int* in_sizes, int n_in,
                              void* d_out, int out_size) {
    const float* x = (const float*)d_in[0];
    const float* gup = (const float*)d_in[1];
    const float* dp = (const float*)d_in[2];
    const int* eidx = (const int*)d_in[3];
    float* out = (float*)d_out;

    cudaFuncSetAttribute(gemm_hmma<D_IN, D_IN / BK, true>,
                         cudaFuncAttributeMaxDynamicSharedMemorySize, SMEM_TOTAL);
    cudaFuncSetAttribute(gemm_hmma<D_MOE, D_MOE / BK, false>,
                         cudaFuncAttributeMaxDynamicSharedMemorySize, SMEM_TOTAL);

    convert_kernel<<<1024, 256>>>(x, gup, dp, eidx);
    // GEMM1 + SwiGLU: h tile 64 wide -> grid (768/64, 4096/128) = (12, 32)
    gemm_hmma<D_IN, D_IN / BK, true><<<dim3(12, 32), 256, SMEM_TOTAL>>>(nullptr);
    // GEMM2: out tile 128 wide -> grid (2048/128, 4096/128) = (16, 32)
    gemm_hmma<D_MOE, D_MOE / BK, false><<<dim3(16, 32), 256, SMEM_TOTAL>>>(out);
}

// round 7
// speedup vs baseline: 1.8745x; 1.2101x over previous
#include <cuda_runtime.h>
#include <cuda_fp16.h>
#include <cstdint>

#define T_TOK 4096
#define D_IN  2048
#define D_MOE 768
#define TWO_DM 1536

// ---- tiling ----
#define BM 128
#define BK 64                       // halves per K chunk = 128B swizzled row
#define A_BYTES  (BM * 128)         // 16 KB
#define B_BYTES  (128 * 128)        // 16 KB (128 B-rows)
#define STAGE_BYTES (A_BYTES + B_BYTES)
#define S_STAGES 3
#define SMEM_TOTAL (S_STAGES * STAGE_BYTES)   // 96 KB -> 2 CTAs/SM = 192 KB

// Scratch (device globals: allocation-free per harness rules)
__device__ __align__(16) __half g_xh[T_TOK * D_IN];      // 16 MB
__device__ __align__(16) __half g_guw[TWO_DM * D_IN];    //  6 MB
__device__ __align__(16) __half g_dw[D_IN * D_MOE];      //  3 MB
__device__ __align__(16) __half g_h[T_TOK * D_MOE];      //  6 MB

// ---------------------------------------------------------------------------
// PTX helpers (all non-'a' features: cp.async sm_80, ldmatrix sm_75, mma sm_80)
// ---------------------------------------------------------------------------
__device__ __forceinline__ uint32_t smem_u32(const void* p) {
    uint32_t a;
    asm("{ .reg .u64 t; cvta.to.shared.u64 t, %1; cvt.u32.u64 %0, t; }" : "=r"(a) : "l"(p));
    return a;
}
__device__ __forceinline__ void cp16(uint32_t saddr, const void* gaddr) {
    asm volatile("cp.async.cg.shared.global [%0], [%1], 16;" :: "r"(saddr), "l"(gaddr));
}
#define CP_COMMIT() asm volatile("cp.async.commit_group;" ::: "memory")
#define CP_WAIT(n)  asm volatile("cp.async.wait_group %0;" :: "n"(n) : "memory")

__device__ __forceinline__ void ldsm_x4(uint32_t& r0, uint32_t& r1, uint32_t& r2, uint32_t& r3,
                                        uint32_t addr) {
    asm volatile("ldmatrix.sync.aligned.m8n8.x4.shared.b16 {%0,%1,%2,%3}, [%4];"
                 : "=r"(r0), "=r"(r1), "=r"(r2), "=r"(r3) : "r"(addr));
}
__device__ __forceinline__ void mma_16816(float* c, const uint32_t* a, const uint32_t* b) {
    asm volatile(
        "mma.sync.aligned.m16n8k16.row.col.f32.f16.f16.f32 "
        "{%0,%1,%2,%3}, {%4,%5,%6,%7}, {%8,%9}, {%0,%1,%2,%3};"
        : "+f"(c[0]), "+f"(c[1]), "+f"(c[2]), "+f"(c[3])
        : "r"(a[0]), "r"(a[1]), "r"(a[2]), "r"(a[3]), "r"(b[0]), "r"(b[1]));
}
__device__ __forceinline__ void st_cs_f2(float* p, float a, float b) {
    asm volatile("st.global.cs.v2.f32 [%0], {%1, %2};" :: "l"(p), "f"(a), "f"(b) : "memory");
}
__device__ __forceinline__ void st_cs_u2(__half* p, uint32_t a, uint32_t b) {
    asm volatile("st.global.cs.v2.b32 [%0], {%1, %2};" :: "l"(p), "r"(a), "r"(b) : "memory");
}
__device__ __forceinline__ float silu_f(float v) { return v / (1.0f + __expf(-v)); }

// ---------------------------------------------------------------------------
// fp32 -> fp16 conversion (float4 vectorized). expert_idx read on device.
// ---------------------------------------------------------------------------
__global__ void convert_kernel(const float* __restrict__ x,
                               const float* __restrict__ gup,
                               const float* __restrict__ dp,
                               const int* __restrict__ eidx) {
    const int e = *eidx;
    const float4* gu4 = (const float4*)(gup + (size_t)e * TWO_DM * D_IN);
    const float4* dw4 = (const float4*)(dp + (size_t)e * D_IN * D_MOE);
    const float4* x4 = (const float4*)x;
    uint2* xo = (uint2*)g_xh;
    uint2* go = (uint2*)g_guw;
    uint2* do_ = (uint2*)g_dw;
    const int stride = gridDim.x * blockDim.x;
    const int tid = blockIdx.x * blockDim.x + threadIdx.x;

    const int nx = T_TOK * D_IN / 4;
    for (int i = tid; i < nx; i += stride) {
        float4 v = x4[i];
        __half2 a = __floats2half2_rn(v.x, v.y), b = __floats2half2_rn(v.z, v.w);
        xo[i] = make_uint2(*(uint32_t*)&a, *(uint32_t*)&b);
    }
    const int ng = TWO_DM * D_IN / 4;
    for (int i = tid; i < ng; i += stride) {
        float4 v = gu4[i];
        __half2 a = __floats2half2_rn(v.x, v.y), b = __floats2half2_rn(v.z, v.w);
        go[i] = make_uint2(*(uint32_t*)&a, *(uint32_t*)&b);
    }
    const int nd = D_IN * D_MOE / 4;
    for (int i = tid; i < nd; i += stride) {
        float4 v = dw4[i];
        __half2 a = __floats2half2_rn(v.x, v.y), b = __floats2half2_rn(v.z, v.w);
        do_[i] = make_uint2(*(uint32_t*)&a, *(uint32_t*)&b);
    }
}

// ---------------------------------------------------------------------------
// Pipelined HMMA GEMM, 2 CTAs/SM. 256 threads = 8 warps (4 M x 2 N).
// Tiles: A 128x64, B 128 rows x 64 (G1: 64 gate + 64 up rows; G2: 128 n rows).
// 3-stage cp.async ring; SW128 swizzle; ldmatrix.x4 fragment loads.
// IS_G1 epilogue: SwiGLU -> g_h (fp16). else: fp32 -> out (streaming stores).
// ---------------------------------------------------------------------------
template <int KDIM, int NCHUNK, bool IS_G1>
__global__ __launch_bounds__(256, 2) void gemm_hmma(float* __restrict__ out) {
    extern __shared__ char smem[];
    const uint32_t sbase = smem_u32(smem);
    const int tid = threadIdx.x, wid = tid >> 5, lane = tid & 31;
    const int wm = wid & 3, wn = wid >> 2;
    const int g = lane >> 2, q = lane & 3;
    const int bn = blockIdx.x, bm = blockIdx.y;

    const __half *Ap, *Bg, *Bu, *Bp;
    if (IS_G1) {
        Ap = g_xh + (size_t)bm * BM * KDIM;
        Bg = g_guw + (size_t)(bn * 64) * KDIM;
        Bu = g_guw + (size_t)(D_MOE + bn * 64) * KDIM;
        Bp = nullptr;
    } else {
        Ap = g_h + (size_t)bm * BM * KDIM;
        Bp = g_dw + (size_t)(bn * 128) * KDIM;
        Bg = Bu = nullptr;
    }

    // ---- stage loader: A 1024 + B 1024 granules of 16B, 8 cp.async/thread ----
    auto load_stage = [&](int stage, int chunk) {
        const uint32_t sA = sbase + stage * STAGE_BYTES;
        const uint32_t sB = sA + A_BYTES;
        const int k0 = chunk * BK;
#pragma unroll
        for (int i = 0; i < 4; i++) {
            int gi = tid + i * 256;
            int r = gi >> 3, c = gi & 7;
            cp16(sA + r * 128 + ((c ^ (r & 7)) << 4), Ap + (size_t)r * KDIM + k0 + c * 8);
        }
#pragma unroll
        for (int i = 0; i < 4; i++) {
            int gi = tid + i * 256;
            int r = gi >> 3, c = gi & 7;
            const __half* src;
            if (IS_G1)
                src = (r < 64) ? (Bg + (size_t)r * KDIM) : (Bu + (size_t)(r - 64) * KDIM);
            else
                src = Bp + (size_t)r * KDIM;
            cp16(sB + r * 128 + ((c ^ (r & 7)) << 4), src + k0 + c * 8);
        }
        CP_COMMIT();
    };

    // ldmatrix lane address components
    const int r7 = lane & 7;
    const int laneRowA = ((lane >> 3) & 1) * 8 + r7;
    const int kselA = lane >> 4;
    const int laneRowB = (lane >> 4) * 8 + r7;
    const int kselB = (lane >> 3) & 1;

    float acc[2][8][4];
#pragma unroll
    for (int a = 0; a < 2; a++)
#pragma unroll
        for (int b = 0; b < 8; b++)
#pragma unroll
            for (int c = 0; c < 4; c++) acc[a][b][c] = 0.f;

    // ---- pipeline ----
    load_stage(0, 0);
    load_stage(1, 1);

    for (int j = 0; j < NCHUNK; j++) {
        if (j == NCHUNK - 1) { CP_WAIT(0); } else { CP_WAIT(1); }
        __syncthreads();
        if (j + 2 < NCHUNK) load_stage((j + 2) % S_STAGES, j + 2);

        const uint32_t sA = sbase + (j % S_STAGES) * STAGE_BYTES;
        const uint32_t sB = sA + A_BYTES;

#pragma unroll
        for (int kk = 0; kk < 4; kk++) {
            uint32_t a[2][4];
#pragma unroll
            for (int mt = 0; mt < 2; mt++) {
                int row = wm * 32 + mt * 16 + laneRowA;
                uint32_t addr = sA + row * 128 + (((kk * 2 + kselA) ^ r7) << 4);
                ldsm_x4(a[mt][0], a[mt][1], a[mt][2], a[mt][3], addr);
            }
            uint32_t b[8][2];
#pragma unroll
            for (int p = 0; p < 4; p++) {
                int nbase;
                if (IS_G1) nbase = (p < 2) ? (wn * 32 + p * 16) : (64 + wn * 32 + (p - 2) * 16);
                else       nbase = wn * 64 + p * 16;
                int row = nbase + laneRowB;
                uint32_t addr = sB + row * 128 + (((kk * 2 + kselB) ^ r7) << 4);
                ldsm_x4(b[2 * p][0], b[2 * p][1], b[2 * p + 1][0], b[2 * p + 1][1], addr);
            }
#pragma unroll
            for (int mt = 0; mt < 2; mt++)
#pragma unroll
                for (int ni = 0; ni < 8; ni++)
                    mma_16816(acc[mt][ni], a[mt], b[ni]);
        }
    }

    // ---- epilogue ----
    if (IS_G1) {
#pragma unroll
        for (int mt = 0; mt < 2; mt++)
#pragma unroll
            for (int ni = 0; ni < 4; ni++) {
                int row = bm * BM + wm * 32 + mt * 16 + g;
                int col = bn * 64 + wn * 32 + ni * 8 + q * 2;
                float* cg = acc[mt][ni];
                float* cu = acc[mt][ni + 4];
                __half2 h01 = __floats2half2_rn(silu_f(cg[0]) * cu[0], silu_f(cg[1]) * cu[1]);
                __half2 h23 = __floats2half2_rn(silu_f(cg[2]) * cu[2], silu_f(cg[3]) * cu[3]);
                *(__half2*)&g_h[(size_t)row * D_MOE + col] = h01;
                *(__half2*)&g_h[(size_t)(row + 8) * D_MOE + col] = h23;
            }
    } else {
#pragma unroll
        for (int mt = 0; mt < 2; mt++)
#pragma unroll
            for (int ni = 0; ni < 8; ni++) {
                int row = bm * BM + wm * 32 + mt * 16 + g;
                int col = bn * 128 + wn * 64 + ni * 8 + q * 2;
                float* c = acc[mt][ni];
                st_cs_f2(&out[(size_t)row * D_IN + col], c[0], c[1]);
                st_cs_f2(&out[(size_t)(row + 8) * D_IN + col], c[2], c[3]);
            }
    }
}

// ---------------------------------------------------------------------------
extern "C" void kernel_launch(void* const* d_in, const int* in_sizes, int n_in,
                              void* d_out, int out_size) {
    const float* x = (const float*)d_in[0];
    const float* gup = (const float*)d_in[1];
    const float* dp = (const float*)d_in[2];
    const int* eidx = (const int*)d_in[3];
    float* out = (float*)d_out;

    cudaFuncSetAttribute(gemm_hmma<D_IN, D_IN / BK, true>,
                         cudaFuncAttributeMaxDynamicSharedMemorySize, SMEM_TOTAL);
    cudaFuncSetAttribute(gemm_hmma<D_MOE, D_MOE / BK, false>,
                         cudaFuncAttributeMaxDynamicSharedMemorySize, SMEM_TOTAL);

    convert_kernel<<<1024, 256>>>(x, gup, dp, eidx);
    // GEMM1 + SwiGLU: h tile 64 wide -> grid (768/64, 4096/128) = (12, 32)
    gemm_hmma<D_IN, D_IN / BK, true><<<dim3(12, 32), 256, SMEM_TOTAL>>>(nullptr);
    // GEMM2: out tile 128 wide -> grid (2048/128, 4096/128) = (16, 32)
    gemm_hmma<D_MOE, D_MOE / BK, false><<<dim3(16, 32), 256, SMEM_TOTAL>>>(out);
}